// round 8
// baseline (speedup 1.0000x reference)
#include <cuda_runtime.h>
#include <cuda_fp16.h>
#include <math.h>
#include <stdint.h>

// ----------------------------------------------------------------------------
// Causal masked softmax attention. N=64, T=1024, D=64.
// BM=128 queries/block (8 warps), BN=64 key tiles.
// cp.async double-buffered raw K/V (tile kt+1 streams in during tile kt's
// compute). K consumed raw by tf32 m16n8k8 (tensor core converts). Flags and
// fp16 V produced by a short post-arrival smem pass overlapped with QK HMMA.
// PV: fp16 m16n8k16, P in registers, V B-fragments via ldmatrix.x4.trans.
// ----------------------------------------------------------------------------

namespace {
constexpr int kT = 1024;
constexpr int BM = 128;
constexpr int BN = 64;
constexpr int kD = 64;
constexpr int THREADS = 256;
constexpr int STRK = 68;   // raw K/V float stride (QK B-load bank 4g+tig bijective)
constexpr int STRVH = 72;  // sVh half stride (rows 144B apart, 16B-aligned)
constexpr float kQScale = 0.18033688011112042f;  // (1/8) * log2(e)
constexpr float kPad = -1e30f;                   // exp2 -> exactly 0
// word offsets into dynamic smem
constexpr int RAWK = 0;                        // [2][BN*STRK] raw fp32 K
constexpr int RAWV = RAWK + 2 * BN * STRK;     // [2][BN*STRK] raw fp32 V
constexpr int SVH  = RAWV + 2 * BN * STRK;     // [BN][36] fp16 V rows (half2)
constexpr int SF   = SVH + BN * (STRVH / 2);   // [BN] |K| row sums
constexpr int SMEM_WORDS = SF + BN;            // 19776 words = 77.25 KB
}  // namespace

__device__ __forceinline__ float ex2f(float x) {
    float r; asm("ex2.approx.ftz.f32 %0, %1;" : "=f"(r) : "f"(x)); return r;
}
__device__ __forceinline__ float tf32r(float x) {
    uint32_t u; asm("cvt.rna.tf32.f32 %0, %1;" : "=r"(u) : "f"(x));
    return __uint_as_float(u);
}
__device__ __forceinline__ uint32_t f2h2(float lo, float hi) {
    __half2 h = __floats2half2_rn(lo, hi);
    return *reinterpret_cast<uint32_t*>(&h);
}
__device__ __forceinline__ void cp16(uint32_t dst_smem, const float* src) {
    asm volatile("cp.async.cg.shared.global [%0], [%1], 16;\n"
                 :: "r"(dst_smem), "l"(src));
}
__device__ __forceinline__ void cp_commit() {
    asm volatile("cp.async.commit_group;\n");
}
__device__ __forceinline__ void cp_wait0() {
    asm volatile("cp.async.wait_group 0;\n");
}
__device__ __forceinline__ void mma_tf32(float (&d)[4],
                                         uint32_t a0, uint32_t a1,
                                         uint32_t a2, uint32_t a3,
                                         uint32_t b0, uint32_t b1) {
    asm volatile(
        "mma.sync.aligned.m16n8k8.row.col.f32.tf32.tf32.f32 "
        "{%0,%1,%2,%3}, {%4,%5,%6,%7}, {%8,%9}, {%0,%1,%2,%3};\n"
        : "+f"(d[0]), "+f"(d[1]), "+f"(d[2]), "+f"(d[3])
        : "r"(a0), "r"(a1), "r"(a2), "r"(a3), "r"(b0), "r"(b1));
}
__device__ __forceinline__ void mma_f16(float (&d)[4],
                                        uint32_t a0, uint32_t a1,
                                        uint32_t a2, uint32_t a3,
                                        uint32_t b0, uint32_t b1) {
    asm volatile(
        "mma.sync.aligned.m16n8k16.row.col.f32.f16.f16.f32 "
        "{%0,%1,%2,%3}, {%4,%5,%6,%7}, {%8,%9}, {%0,%1,%2,%3};\n"
        : "+f"(d[0]), "+f"(d[1]), "+f"(d[2]), "+f"(d[3])
        : "r"(a0), "r"(a1), "r"(a2), "r"(a3), "r"(b0), "r"(b1));
}
__device__ __forceinline__ void ldsm_x4_trans(uint32_t& r0, uint32_t& r1,
                                              uint32_t& r2, uint32_t& r3,
                                              uint32_t addr) {
    asm volatile(
        "ldmatrix.sync.aligned.m8n8.x4.trans.shared.b16 {%0,%1,%2,%3}, [%4];\n"
        : "=r"(r0), "=r"(r1), "=r"(r2), "=r"(r3) : "r"(addr));
}

__global__ __launch_bounds__(THREADS, 2)
void attn_cpasync_kernel(const float* __restrict__ Q,
                         const float* __restrict__ K,
                         const float* __restrict__ V,
                         float* __restrict__ O) {
    extern __shared__ float sm[];
    uint32_t* sVh2 = (uint32_t*)(sm + SVH);    // [BN][36] half2
    float* sF = sm + SF;

    const int tid = threadIdx.x;
    const int warp = tid >> 5;   // 0..7
    const int lane = tid & 31;
    const int g = lane >> 2;
    const int tig = lane & 3;
    const int qt = (kT / BM - 1) - blockIdx.x;   // heavy q-tiles first
    const int bn = blockIdx.y;
    const int q0 = qt * BM;

    const float* Qg = Q + ((size_t)bn * kT + q0) * kD;
    const float* Kg = K + (size_t)bn * kT * kD;
    const float* Vg = V + (size_t)bn * kT * kD;

    const int tx = tid & 15, ty = tid >> 4;      // 16x16 loader layout
    const uint32_t smem_u32 = (uint32_t)__cvta_generic_to_shared(sm);

    // ---- stage Q (scaled, rna-tf32) through rawK buf0 in two passes ---------
    float* sQ = sm + RAWK;
    uint32_t qf[8][4];
#pragma unroll
    for (int p = 0; p < 2; p++) {
        if (p) __syncthreads();
#pragma unroll
        for (int i = 0; i < 4; i++) {
            const int r = ty + 16 * i;
            float4 qv = *(const float4*)(Qg + (size_t)(64 * p + r) * kD + 4 * tx);
            *(float4*)(sQ + r * STRK + 4 * tx) =
                make_float4(tf32r(qv.x * kQScale), tf32r(qv.y * kQScale),
                            tf32r(qv.z * kQScale), tf32r(qv.w * kQScale));
        }
        __syncthreads();
        if ((warp >> 2) == p) {
            const float* mq = sQ + ((warp & 3) * 16) * STRK;
#pragma unroll
            for (int kb = 0; kb < 8; kb++) {
                qf[kb][0] = __float_as_uint(mq[g * STRK + kb * 8 + tig]);
                qf[kb][1] = __float_as_uint(mq[(g + 8) * STRK + kb * 8 + tig]);
                qf[kb][2] = __float_as_uint(mq[g * STRK + kb * 8 + tig + 4]);
                qf[kb][3] = __float_as_uint(mq[(g + 8) * STRK + kb * 8 + tig + 4]);
            }
        }
    }
    __syncthreads();   // all qf reads done before cp.async overwrites buf0

    // issue one tile's K+V loads into buffer parity p (8 cp.async, 1 group)
    auto issue_tile = [&](int k0, int p) {
#pragma unroll
        for (int i = 0; i < 4; i++) {
            const int r = ty + 16 * i;
            cp16(smem_u32 + 4 * (RAWK + p * BN * STRK + r * STRK + 4 * tx),
                 Kg + (size_t)(k0 + r) * kD + 4 * tx);
            cp16(smem_u32 + 4 * (RAWV + p * BN * STRK + r * STRK + 4 * tx),
                 Vg + (size_t)(k0 + r) * kD + 4 * tx);
        }
        cp_commit();
    };

    issue_tile(0, 0);   // prologue: tile 0 in flight

    float m0 = kPad, m1 = kPad, l0 = 0.f, l1 = 0.f;
    float o[8][4];
#pragma unroll
    for (int nb = 0; nb < 8; nb++)
#pragma unroll
        for (int j = 0; j < 4; j++) o[nb][j] = 0.f;

    const int rowg0 = q0 + warp * 16 + g;
    const int rowg1 = rowg0 + 8;
    const uint32_t vbase = smem_u32 + 4 * SVH;
    const uint32_t lrow = lane & 15, lhi = lane >> 4;
    // flags / V-convert role: 4 threads per key row
    const int fr = tid >> 2;       // row 0..63
    const int fc = tid & 3;        // 16-float chunk

    const int nkt = 2 * qt + 2;
    for (int kt = 0; kt < nkt; kt++) {
        const int k0 = kt * BN;
        const int p = kt & 1;

        cp_wait0();          // tile kt's raw K/V arrived (this thread's view)
        __syncthreads();     // everyone arrived + done with tile kt-1

        if (kt + 1 < nkt) issue_tile(k0 + BN, (kt + 1) & 1);  // overlap w/ compute

        const float* rK = sm + RAWK + p * BN * STRK;
        const bool active = (k0 <= q0 + warp * 16 + 15);

        // ---- S = Q K^T (tf32; K raw fp32, tensor core converts) -------------
        float s[8][4];
        if (active) {
#pragma unroll
            for (int nb = 0; nb < 8; nb++)
#pragma unroll
                for (int j = 0; j < 4; j++) s[nb][j] = 0.f;
#pragma unroll
            for (int kb = 0; kb < 8; kb++) {
#pragma unroll
                for (int nb = 0; nb < 8; nb++) {
                    const float* kp = rK + (nb * 8 + g) * STRK + kb * 8 + tig;
                    mma_tf32(s[nb], qf[kb][0], qf[kb][1], qf[kb][2], qf[kb][3],
                             __float_as_uint(kp[0]), __float_as_uint(kp[4]));
                }
            }
        }

        // ---- flags + V fp16 conversion (all threads; overlaps HMMA drain) ---
        {
            const float* kr = rK + fr * STRK + 16 * fc;
            float4 ka = *(const float4*)(kr + 0);
            float4 kb4 = *(const float4*)(kr + 4);
            float4 kc = *(const float4*)(kr + 8);
            float4 kd = *(const float4*)(kr + 12);
            float asum = fabsf(ka.x) + fabsf(ka.y) + fabsf(ka.z) + fabsf(ka.w)
                       + fabsf(kb4.x) + fabsf(kb4.y) + fabsf(kb4.z) + fabsf(kb4.w)
                       + fabsf(kc.x) + fabsf(kc.y) + fabsf(kc.z) + fabsf(kc.w)
                       + fabsf(kd.x) + fabsf(kd.y) + fabsf(kd.z) + fabsf(kd.w);
            asum += __shfl_xor_sync(0xffffffffu, asum, 1);
            asum += __shfl_xor_sync(0xffffffffu, asum, 2);
            if (fc == 0) sF[fr] = asum;

            const float* vr = sm + RAWV + p * BN * STRK + fr * STRK + 16 * fc;
            float4 va = *(const float4*)(vr + 0);
            float4 vb = *(const float4*)(vr + 4);
            float4 vc = *(const float4*)(vr + 8);
            float4 vd = *(const float4*)(vr + 12);
            uint32_t* dh = sVh2 + fr * (STRVH / 2) + 8 * fc;
            *(uint4*)(dh + 0) = make_uint4(f2h2(va.x, va.y), f2h2(va.z, va.w),
                                           f2h2(vb.x, vb.y), f2h2(vb.z, vb.w));
            *(uint4*)(dh + 4) = make_uint4(f2h2(vc.x, vc.y), f2h2(vc.z, vc.w),
                                           f2h2(vd.x, vd.y), f2h2(vd.z, vd.w));
        }
        __syncthreads();     // sF + sVh complete for all rows

        if (!active) continue;

        // ---- masks ----------------------------------------------------------
        const bool needC = (k0 + BN - 1 > q0 + warp * 16);
#pragma unroll
        for (int nb = 0; nb < 8; nb++) {
            const int c = k0 + nb * 8 + 2 * tig;
            const float f0 = sF[nb * 8 + 2 * tig];
            const float f1 = sF[nb * 8 + 2 * tig + 1];
            if (f0 == 0.f) { s[nb][0] = kPad; s[nb][2] = kPad; }
            if (f1 == 0.f) { s[nb][1] = kPad; s[nb][3] = kPad; }
            if (needC) {
                if (c > rowg0)     s[nb][0] = kPad;
                if (c + 1 > rowg0) s[nb][1] = kPad;
                if (c > rowg1)     s[nb][2] = kPad;
                if (c + 1 > rowg1) s[nb][3] = kPad;
            }
        }

        // ---- online softmax (base 2), P in registers ------------------------
        float rmax0 = kPad, rmax1 = kPad;
#pragma unroll
        for (int nb = 0; nb < 8; nb++) {
            rmax0 = fmaxf(rmax0, fmaxf(s[nb][0], s[nb][1]));
            rmax1 = fmaxf(rmax1, fmaxf(s[nb][2], s[nb][3]));
        }
        rmax0 = fmaxf(rmax0, __shfl_xor_sync(0xffffffffu, rmax0, 1));
        rmax0 = fmaxf(rmax0, __shfl_xor_sync(0xffffffffu, rmax0, 2));
        rmax1 = fmaxf(rmax1, __shfl_xor_sync(0xffffffffu, rmax1, 1));
        rmax1 = fmaxf(rmax1, __shfl_xor_sync(0xffffffffu, rmax1, 2));
        const float mn0 = fmaxf(m0, rmax0);
        const float mn1 = fmaxf(m1, rmax1);
        const float corr0 = ex2f(m0 - mn0);
        const float corr1 = ex2f(m1 - mn1);
        float rs0 = 0.f, rs1 = 0.f;
#pragma unroll
        for (int nb = 0; nb < 8; nb++) {
            s[nb][0] = ex2f(s[nb][0] - mn0);
            s[nb][1] = ex2f(s[nb][1] - mn0);
            s[nb][2] = ex2f(s[nb][2] - mn1);
            s[nb][3] = ex2f(s[nb][3] - mn1);
            rs0 += s[nb][0] + s[nb][1];
            rs1 += s[nb][2] + s[nb][3];
        }
        rs0 += __shfl_xor_sync(0xffffffffu, rs0, 1);
        rs0 += __shfl_xor_sync(0xffffffffu, rs0, 2);
        rs1 += __shfl_xor_sync(0xffffffffu, rs1, 1);
        rs1 += __shfl_xor_sync(0xffffffffu, rs1, 2);
        l0 = l0 * corr0 + rs0; m0 = mn0;
        l1 = l1 * corr1 + rs1; m1 = mn1;
#pragma unroll
        for (int nb = 0; nb < 8; nb++) {
            o[nb][0] *= corr0; o[nb][1] *= corr0;
            o[nb][2] *= corr1; o[nb][3] *= corr1;
        }

        // ---- O += P V (fp16; B via ldmatrix.x4.trans) -----------------------
#pragma unroll
        for (int t = 0; t < 4; t++) {
            const uint32_t a0 = f2h2(s[2 * t][0], s[2 * t][1]);
            const uint32_t a1 = f2h2(s[2 * t][2], s[2 * t][3]);
            const uint32_t a2 = f2h2(s[2 * t + 1][0], s[2 * t + 1][1]);
            const uint32_t a3 = f2h2(s[2 * t + 1][2], s[2 * t + 1][3]);
            const uint32_t addr0 = vbase + ((16 * t + lrow) * STRVH + 8 * lhi) * 2;
#pragma unroll
            for (int nbp = 0; nbp < 4; nbp++) {
                uint32_t b0, b1, b2, b3;
                ldsm_x4_trans(b0, b1, b2, b3, addr0 + nbp * 32);
                mma_f16(o[2 * nbp], a0, a1, a2, a3, b0, b1);
                mma_f16(o[2 * nbp + 1], a0, a1, a2, a3, b2, b3);
            }
        }
    }

    // ---- finalize -----------------------------------------------------------
    const float inv0 = 1.f / l0;
    const float inv1 = 1.f / l1;
    float* Og = O + (size_t)bn * kT * kD;
#pragma unroll
    for (int nb = 0; nb < 8; nb++) {
        *(float2*)(Og + (size_t)rowg0 * kD + nb * 8 + 2 * tig) =
            make_float2(o[nb][0] * inv0, o[nb][1] * inv0);
        *(float2*)(Og + (size_t)rowg1 * kD + nb * 8 + 2 * tig) =
            make_float2(o[nb][2] * inv1, o[nb][3] * inv1);
    }
}

extern "C" void kernel_launch(void* const* d_in, const int* in_sizes, int n_in,
                              void* d_out, int out_size) {
    const float* q = (const float*)d_in[0];
    const float* k = (const float*)d_in[1];
    const float* v = (const float*)d_in[2];
    float* o = (float*)d_out;

    const size_t smem_bytes = (size_t)SMEM_WORDS * sizeof(float);  // 77.25 KB
    cudaFuncSetAttribute(attn_cpasync_kernel,
                         cudaFuncAttributeMaxDynamicSharedMemorySize,
                         (int)smem_bytes);

    dim3 grid(kT / BM, 64);   // 8 x 64 = 512 blocks
    attn_cpasync_kernel<<<grid, THREADS, smem_bytes>>>(q, k, v, o);
}

// round 9
// speedup vs baseline: 1.5903x; 1.5903x over previous
#include <cuda_runtime.h>
#include <cuda_fp16.h>
#include <math.h>
#include <stdint.h>

// ----------------------------------------------------------------------------
// Causal masked softmax attention. N=64, T=1024, D=64.
// BM=128 queries/block (8 warps), BN=64 key tiles. All-fp16 tensor GEMMs
// (fp16 mantissa == tf32 mantissa), fp32 accumulators, fp32 softmax.
//   QK^T: m16n8k16, A=Q regs (ldmatrix.x4 once), B=K via ldmatrix.x4 non-trans.
//   PV:   m16n8k16, A=P regs (C-layout == A-layout), B=V via ldmatrix.x4.trans.
// K and V stored fp16 row-major stride 72 halves (144B rows -> ldmatrix
// conflict-free). Flags from raw fp32 K at load. Synchronous double-use
// loader (R7 skeleton; cp.async experiment reverted after R8 regression).
// ----------------------------------------------------------------------------

namespace {
constexpr int kT = 1024;
constexpr int BM = 128;
constexpr int BN = 64;
constexpr int kD = 64;
constexpr int THREADS = 256;
constexpr int STRH = 72;      // row stride in halves (144 B)
constexpr float kQScale = 0.18033688011112042f;  // (1/8) * log2(e)
constexpr float kPad = -1e30f;                   // exp2 -> exactly 0
// layout (halves): K rows [0,64) at 0; V rows [0,64) at 64*72.
// Q staging uses rows [0,128) over the same span (consumed before K/V load).
constexpr int VOFF_H = BN * STRH;                // 4608 halves
constexpr int SF_W = BN * STRH;                  // word offset 4608 = flags
constexpr int SMEM_WORDS = SF_W + BN;            // 4672 words = 18.25 KB
}  // namespace

__device__ __forceinline__ float ex2f(float x) {
    float r; asm("ex2.approx.ftz.f32 %0, %1;" : "=f"(r) : "f"(x)); return r;
}
__device__ __forceinline__ uint32_t f2h2(float lo, float hi) {
    __half2 h = __floats2half2_rn(lo, hi);
    return *reinterpret_cast<uint32_t*>(&h);
}
__device__ __forceinline__ void mma_f16(float (&d)[4],
                                        uint32_t a0, uint32_t a1,
                                        uint32_t a2, uint32_t a3,
                                        uint32_t b0, uint32_t b1) {
    asm volatile(
        "mma.sync.aligned.m16n8k16.row.col.f32.f16.f16.f32 "
        "{%0,%1,%2,%3}, {%4,%5,%6,%7}, {%8,%9}, {%0,%1,%2,%3};\n"
        : "+f"(d[0]), "+f"(d[1]), "+f"(d[2]), "+f"(d[3])
        : "r"(a0), "r"(a1), "r"(a2), "r"(a3), "r"(b0), "r"(b1));
}
__device__ __forceinline__ void ldsm_x4(uint32_t& r0, uint32_t& r1,
                                        uint32_t& r2, uint32_t& r3,
                                        uint32_t addr) {
    asm volatile(
        "ldmatrix.sync.aligned.m8n8.x4.shared.b16 {%0,%1,%2,%3}, [%4];\n"
        : "=r"(r0), "=r"(r1), "=r"(r2), "=r"(r3) : "r"(addr));
}
__device__ __forceinline__ void ldsm_x4_trans(uint32_t& r0, uint32_t& r1,
                                              uint32_t& r2, uint32_t& r3,
                                              uint32_t addr) {
    asm volatile(
        "ldmatrix.sync.aligned.m8n8.x4.trans.shared.b16 {%0,%1,%2,%3}, [%4];\n"
        : "=r"(r0), "=r"(r1), "=r"(r2), "=r"(r3) : "r"(addr));
}

__global__ __launch_bounds__(THREADS, 2)
void attn_fp16_kernel(const float* __restrict__ Q, const float* __restrict__ K,
                      const float* __restrict__ V, float* __restrict__ O) {
    extern __shared__ float sm[];
    uint32_t* sH2 = (uint32_t*)sm;             // K/V/Q halves region (as half2)
    float* sF = sm + SF_W;                     // [BN] |K| row sums

    const int tid = threadIdx.x;
    const int warp = tid >> 5;   // 0..7
    const int lane = tid & 31;
    const int g = lane >> 2;
    const int tig = lane & 3;
    const int qt = (kT / BM - 1) - blockIdx.x;   // heavy q-tiles first
    const int bn = blockIdx.y;
    const int q0 = qt * BM;

    const float* Qg = Q + ((size_t)bn * kT + q0) * kD;
    const float* Kg = K + (size_t)bn * kT * kD;
    const float* Vg = V + (size_t)bn * kT * kD;

    const int tx = tid & 15, ty = tid >> 4;      // 16x16 loader layout
    const uint32_t base = (uint32_t)__cvta_generic_to_shared(sm);  // bytes
    const uint32_t vbase = base + 2 * VOFF_H;

    // ---- stage Q (scaled fp16) across rows 0..127, then fragment ------------
#pragma unroll
    for (int i = 0; i < 8; i++) {
        const int r = ty + 16 * i;               // 0..127
        float4 qv = *(const float4*)(Qg + (size_t)r * kD + 4 * tx);
        *(uint2*)(sH2 + r * (STRH / 2) + 2 * tx) =
            make_uint2(f2h2(qv.x * kQScale, qv.y * kQScale),
                       f2h2(qv.z * kQScale, qv.w * kQScale));
    }
    __syncthreads();
    // A fragments: m0=rows g,klo  m1=rows g+8,klo  m2=rows g,khi  m3=rows g+8,khi
    uint32_t qf[4][4];
    {
        const uint32_t qrow = warp * 16 + ((lane >> 3) & 1) * 8 + (lane & 7);
        const uint32_t qaddr = base + (qrow * STRH + 8 * (lane >> 4)) * 2;
#pragma unroll
        for (int kb = 0; kb < 4; kb++)
            ldsm_x4(qf[kb][0], qf[kb][1], qf[kb][2], qf[kb][3],
                    qaddr + 32 * kb);
    }

    float m0 = kPad, m1 = kPad, l0 = 0.f, l1 = 0.f;
    float o[8][4];
#pragma unroll
    for (int nb = 0; nb < 8; nb++)
#pragma unroll
        for (int j = 0; j < 4; j++) o[nb][j] = 0.f;

    const int rowg0 = q0 + warp * 16 + g;
    const int rowg1 = rowg0 + 8;
    const uint32_t lrow = lane & 15, lhi = lane >> 4;
    // K ldmatrix lane address pieces: m0={keys lo, dims lo} m1={keys lo, dims hi}
    //                                 m2={keys hi, dims lo} m3={keys hi, dims hi}
    const uint32_t krow_in16 = 8 * (lane >> 4) + (lane & 7);
    const uint32_t kdim8 = 8 * ((lane >> 3) & 1);

    const int nkt = 2 * qt + 2;                  // key tiles with keys <= q0+127
    for (int kt = 0; kt < nkt; kt++) {
        const int k0 = kt * BN;
        __syncthreads();   // prior tile's ldmatrix reads done (also Q frag reads)

        // ---- load K + flags, V; convert both to fp16 rows -------------------
#pragma unroll
        for (int i = 0; i < 4; i++) {
            const int r = ty + 16 * i;           // 0..63
            float4 kv = *(const float4*)(Kg + (size_t)(k0 + r) * kD + 4 * tx);
            float asum = fabsf(kv.x) + fabsf(kv.y) + fabsf(kv.z) + fabsf(kv.w);
#pragma unroll
            for (int off = 8; off > 0; off >>= 1)
                asum += __shfl_xor_sync(0xffffffffu, asum, off, 16);
            if (tx == 0) sF[r] = asum;
            *(uint2*)(sH2 + r * (STRH / 2) + 2 * tx) =
                make_uint2(f2h2(kv.x, kv.y), f2h2(kv.z, kv.w));
            float4 vv = *(const float4*)(Vg + (size_t)(k0 + r) * kD + 4 * tx);
            *(uint2*)(sH2 + (VOFF_H / 2) + r * (STRH / 2) + 2 * tx) =
                make_uint2(f2h2(vv.x, vv.y), f2h2(vv.z, vv.w));
        }
        __syncthreads();

        const bool active = (k0 <= q0 + warp * 16 + 15);
        if (!active) continue;                   // barriers already passed

        // ---- S = Q K^T (fp16 m16n8k16; B via ldmatrix.x4 non-trans) ---------
        float s[8][4];
#pragma unroll
        for (int nb = 0; nb < 8; nb++)
#pragma unroll
            for (int j = 0; j < 4; j++) s[nb][j] = 0.f;
#pragma unroll
        for (int kb = 0; kb < 4; kb++) {
#pragma unroll
            for (int nbp = 0; nbp < 4; nbp++) {  // 16-key groups
                const uint32_t kaddr =
                    base + ((16 * nbp + krow_in16) * STRH + 16 * kb + kdim8) * 2;
                uint32_t b0, b1, b2, b3;
                ldsm_x4(b0, b1, b2, b3, kaddr);
                mma_f16(s[2 * nbp], qf[kb][0], qf[kb][1], qf[kb][2], qf[kb][3],
                        b0, b1);
                mma_f16(s[2 * nbp + 1], qf[kb][0], qf[kb][1], qf[kb][2],
                        qf[kb][3], b2, b3);
            }
        }

        // ---- masks ----------------------------------------------------------
        const bool needC = (k0 + BN - 1 > q0 + warp * 16);
#pragma unroll
        for (int nb = 0; nb < 8; nb++) {
            const int c = k0 + nb * 8 + 2 * tig;
            const float f0 = sF[nb * 8 + 2 * tig];
            const float f1 = sF[nb * 8 + 2 * tig + 1];
            if (f0 == 0.f) { s[nb][0] = kPad; s[nb][2] = kPad; }
            if (f1 == 0.f) { s[nb][1] = kPad; s[nb][3] = kPad; }
            if (needC) {
                if (c > rowg0)     s[nb][0] = kPad;
                if (c + 1 > rowg0) s[nb][1] = kPad;
                if (c > rowg1)     s[nb][2] = kPad;
                if (c + 1 > rowg1) s[nb][3] = kPad;
            }
        }

        // ---- online softmax (base 2), P in registers ------------------------
        float rmax0 = kPad, rmax1 = kPad;
#pragma unroll
        for (int nb = 0; nb < 8; nb++) {
            rmax0 = fmaxf(rmax0, fmaxf(s[nb][0], s[nb][1]));
            rmax1 = fmaxf(rmax1, fmaxf(s[nb][2], s[nb][3]));
        }
        rmax0 = fmaxf(rmax0, __shfl_xor_sync(0xffffffffu, rmax0, 1));
        rmax0 = fmaxf(rmax0, __shfl_xor_sync(0xffffffffu, rmax0, 2));
        rmax1 = fmaxf(rmax1, __shfl_xor_sync(0xffffffffu, rmax1, 1));
        rmax1 = fmaxf(rmax1, __shfl_xor_sync(0xffffffffu, rmax1, 2));
        const float mn0 = fmaxf(m0, rmax0);
        const float mn1 = fmaxf(m1, rmax1);
        const float corr0 = ex2f(m0 - mn0);
        const float corr1 = ex2f(m1 - mn1);
        float rs0 = 0.f, rs1 = 0.f;
#pragma unroll
        for (int nb = 0; nb < 8; nb++) {
            s[nb][0] = ex2f(s[nb][0] - mn0);
            s[nb][1] = ex2f(s[nb][1] - mn0);
            s[nb][2] = ex2f(s[nb][2] - mn1);
            s[nb][3] = ex2f(s[nb][3] - mn1);
            rs0 += s[nb][0] + s[nb][1];
            rs1 += s[nb][2] + s[nb][3];
        }
        rs0 += __shfl_xor_sync(0xffffffffu, rs0, 1);
        rs0 += __shfl_xor_sync(0xffffffffu, rs0, 2);
        rs1 += __shfl_xor_sync(0xffffffffu, rs1, 1);
        rs1 += __shfl_xor_sync(0xffffffffu, rs1, 2);
        l0 = l0 * corr0 + rs0; m0 = mn0;
        l1 = l1 * corr1 + rs1; m1 = mn1;
#pragma unroll
        for (int nb = 0; nb < 8; nb++) {
            o[nb][0] *= corr0; o[nb][1] *= corr0;
            o[nb][2] *= corr1; o[nb][3] *= corr1;
        }

        // ---- O += P V (fp16; B via ldmatrix.x4.trans, as validated) ---------
#pragma unroll
        for (int t = 0; t < 4; t++) {
            const uint32_t a0 = f2h2(s[2 * t][0], s[2 * t][1]);
            const uint32_t a1 = f2h2(s[2 * t][2], s[2 * t][3]);
            const uint32_t a2 = f2h2(s[2 * t + 1][0], s[2 * t + 1][1]);
            const uint32_t a3 = f2h2(s[2 * t + 1][2], s[2 * t + 1][3]);
            const uint32_t addr0 = vbase + ((16 * t + lrow) * STRH + 8 * lhi) * 2;
#pragma unroll
            for (int nbp = 0; nbp < 4; nbp++) {
                uint32_t b0, b1, b2, b3;
                ldsm_x4_trans(b0, b1, b2, b3, addr0 + nbp * 32);
                mma_f16(o[2 * nbp], a0, a1, a2, a3, b0, b1);
                mma_f16(o[2 * nbp + 1], a0, a1, a2, a3, b2, b3);
            }
        }
    }

    // ---- finalize -----------------------------------------------------------
    const float inv0 = 1.f / l0;
    const float inv1 = 1.f / l1;
    float* Og = O + (size_t)bn * kT * kD;
#pragma unroll
    for (int nb = 0; nb < 8; nb++) {
        *(float2*)(Og + (size_t)rowg0 * kD + nb * 8 + 2 * tig) =
            make_float2(o[nb][0] * inv0, o[nb][1] * inv0);
        *(float2*)(Og + (size_t)rowg1 * kD + nb * 8 + 2 * tig) =
            make_float2(o[nb][2] * inv1, o[nb][3] * inv1);
    }
}

extern "C" void kernel_launch(void* const* d_in, const int* in_sizes, int n_in,
                              void* d_out, int out_size) {
    const float* q = (const float*)d_in[0];
    const float* k = (const float*)d_in[1];
    const float* v = (const float*)d_in[2];
    float* o = (float*)d_out;

    const size_t smem_bytes = (size_t)SMEM_WORDS * sizeof(float);  // 18.25 KB
    cudaFuncSetAttribute(attn_fp16_kernel,
                         cudaFuncAttributeMaxDynamicSharedMemorySize,
                         (int)smem_bytes);

    dim3 grid(kT / BM, 64);   // 8 x 64 = 512 blocks
    attn_fp16_kernel<<<grid, THREADS, smem_bytes>>>(q, k, v, o);
}

// round 10
// speedup vs baseline: 1.6915x; 1.0637x over previous
#include <cuda_runtime.h>
#include <cuda_fp16.h>
#include <math.h>
#include <stdint.h>

// ----------------------------------------------------------------------------
// Causal masked softmax attention. N=64, T=1024, D=64.
// BM=128 queries/block (8 warps). K/V loaded in 128-key rounds (one barrier
// pair per round), computed as two 64-key chunks. All-fp16 tensor GEMMs
// (fp16 mantissa == tf32 mantissa), fp32 accumulators, fp32 softmax.
//   QK^T: m16n8k16, A=Q regs (ldmatrix.x4 once), B=K via ldmatrix.x4 non-trans.
//   PV:   m16n8k16, A=P regs (C-layout == A-layout), B=V via ldmatrix.x4.trans.
// Key-padding mask as additive bias (0 / -1e30) computed at load from raw K.
// ----------------------------------------------------------------------------

namespace {
constexpr int kT = 1024;
constexpr int BM = 128;
constexpr int BK2 = 128;     // keys per load round (2 x 64-key compute chunks)
constexpr int kD = 64;
constexpr int THREADS = 256;
constexpr int STRH = 72;     // row stride in halves (144 B; ldmatrix conflict-free)
constexpr float kQScale = 0.18033688011112042f;  // (1/8) * log2(e)
constexpr float kPad = -1e30f;                   // exp2 -> exactly 0
constexpr int VOFF_H = BK2 * STRH;               // 9216 halves: V region start
constexpr int SB_W = VOFF_H;                     // word 9216: bias array
constexpr int SMEM_WORDS = SB_W + BK2;           // 9344 words = 36.5 KB
}  // namespace

__device__ __forceinline__ float ex2f(float x) {
    float r; asm("ex2.approx.ftz.f32 %0, %1;" : "=f"(r) : "f"(x)); return r;
}
__device__ __forceinline__ uint32_t f2h2(float lo, float hi) {
    __half2 h = __floats2half2_rn(lo, hi);
    return *reinterpret_cast<uint32_t*>(&h);
}
__device__ __forceinline__ void mma_f16(float (&d)[4],
                                        uint32_t a0, uint32_t a1,
                                        uint32_t a2, uint32_t a3,
                                        uint32_t b0, uint32_t b1) {
    asm volatile(
        "mma.sync.aligned.m16n8k16.row.col.f32.f16.f16.f32 "
        "{%0,%1,%2,%3}, {%4,%5,%6,%7}, {%8,%9}, {%0,%1,%2,%3};\n"
        : "+f"(d[0]), "+f"(d[1]), "+f"(d[2]), "+f"(d[3])
        : "r"(a0), "r"(a1), "r"(a2), "r"(a3), "r"(b0), "r"(b1));
}
__device__ __forceinline__ void ldsm_x4(uint32_t& r0, uint32_t& r1,
                                        uint32_t& r2, uint32_t& r3,
                                        uint32_t addr) {
    asm volatile(
        "ldmatrix.sync.aligned.m8n8.x4.shared.b16 {%0,%1,%2,%3}, [%4];\n"
        : "=r"(r0), "=r"(r1), "=r"(r2), "=r"(r3) : "r"(addr));
}
__device__ __forceinline__ void ldsm_x4_trans(uint32_t& r0, uint32_t& r1,
                                              uint32_t& r2, uint32_t& r3,
                                              uint32_t addr) {
    asm volatile(
        "ldmatrix.sync.aligned.m8n8.x4.trans.shared.b16 {%0,%1,%2,%3}, [%4];\n"
        : "=r"(r0), "=r"(r1), "=r"(r2), "=r"(r3) : "r"(addr));
}

__global__ __launch_bounds__(THREADS, 2)
void attn_fp16_r2_kernel(const float* __restrict__ Q,
                         const float* __restrict__ K,
                         const float* __restrict__ V,
                         float* __restrict__ O) {
    extern __shared__ float sm[];
    uint32_t* sH2 = (uint32_t*)sm;             // K/V halves region (as half2)
    float* sB = sm + SB_W;                     // [BK2] additive pad bias

    const int tid = threadIdx.x;
    const int warp = tid >> 5;   // 0..7
    const int lane = tid & 31;
    const int g = lane >> 2;
    const int tig = lane & 3;
    const int qt = (kT / BM - 1) - blockIdx.x;   // heavy q-tiles first
    const int bn = blockIdx.y;
    const int q0 = qt * BM;

    const float* Qg = Q + ((size_t)bn * kT + q0) * kD;
    const float* Kg = K + (size_t)bn * kT * kD;
    const float* Vg = V + (size_t)bn * kT * kD;

    const int tx = tid & 15, ty = tid >> 4;      // 16x16 loader layout
    const uint32_t base = (uint32_t)__cvta_generic_to_shared(sm);  // bytes
    const uint32_t vbase = base + 2 * VOFF_H;

    // ---- stage Q (scaled fp16) across rows 0..127 in the K region -----------
#pragma unroll
    for (int i = 0; i < 8; i++) {
        const int r = ty + 16 * i;               // 0..127
        float4 qv = *(const float4*)(Qg + (size_t)r * kD + 4 * tx);
        *(uint2*)(sH2 + r * (STRH / 2) + 2 * tx) =
            make_uint2(f2h2(qv.x * kQScale, qv.y * kQScale),
                       f2h2(qv.z * kQScale, qv.w * kQScale));
    }
    __syncthreads();
    // A fragments via ldmatrix.x4 (rows g/g+8, k halves per kb)
    uint32_t qf[4][4];
    {
        const uint32_t qrow = warp * 16 + ((lane >> 3) & 1) * 8 + (lane & 7);
        const uint32_t qaddr = base + (qrow * STRH + 8 * (lane >> 4)) * 2;
#pragma unroll
        for (int kb = 0; kb < 4; kb++)
            ldsm_x4(qf[kb][0], qf[kb][1], qf[kb][2], qf[kb][3],
                    qaddr + 32 * kb);
    }

    float m0 = kPad, m1 = kPad, l0 = 0.f, l1 = 0.f;
    float o[8][4];
#pragma unroll
    for (int nb = 0; nb < 8; nb++)
#pragma unroll
        for (int j = 0; j < 4; j++) o[nb][j] = 0.f;

    const int rowg0 = q0 + warp * 16 + g;
    const int rowg1 = rowg0 + 8;
    const uint32_t lrow = lane & 15, lhi = lane >> 4;
    const uint32_t krow_in16 = 8 * (lane >> 4) + (lane & 7);
    const uint32_t kdim8 = 8 * ((lane >> 3) & 1);

    const int nrounds = qt + 1;                  // 128-key rounds
    for (int rd = 0; rd < nrounds; rd++) {
        const int k0r = rd * BK2;
        __syncthreads();   // prior round's ldmatrix reads done (also Q staging)

        // ---- load 128 K rows (+bias) and 128 V rows, fp16-convert -----------
#pragma unroll
        for (int i = 0; i < 8; i++) {
            const int r = ty + 16 * i;           // 0..127
            float4 kv = *(const float4*)(Kg + (size_t)(k0r + r) * kD + 4 * tx);
            float asum = fabsf(kv.x) + fabsf(kv.y) + fabsf(kv.z) + fabsf(kv.w);
#pragma unroll
            for (int off = 8; off > 0; off >>= 1)
                asum += __shfl_xor_sync(0xffffffffu, asum, off, 16);
            if (tx == 0) sB[r] = (asum == 0.f) ? kPad : 0.f;
            *(uint2*)(sH2 + r * (STRH / 2) + 2 * tx) =
                make_uint2(f2h2(kv.x, kv.y), f2h2(kv.z, kv.w));
            float4 vv = *(const float4*)(Vg + (size_t)(k0r + r) * kD + 4 * tx);
            *(uint2*)(sH2 + (VOFF_H / 2) + r * (STRH / 2) + 2 * tx) =
                make_uint2(f2h2(vv.x, vv.y), f2h2(vv.z, vv.w));
        }
        __syncthreads();

        // ---- two 64-key compute chunks from this round ----------------------
#pragma unroll
        for (int c = 0; c < 2; c++) {
            const int k0 = k0r + 64 * c;
            if (k0 > q0 + warp * 16 + 15) continue;   // no barriers inside
            const int rb = 64 * c;                    // smem row base

            // S = Q K^T
            float s[8][4];
#pragma unroll
            for (int nb = 0; nb < 8; nb++)
#pragma unroll
                for (int j = 0; j < 4; j++) s[nb][j] = 0.f;
#pragma unroll
            for (int kb = 0; kb < 4; kb++) {
#pragma unroll
                for (int nbp = 0; nbp < 4; nbp++) {
                    const uint32_t kaddr =
                        base + ((rb + 16 * nbp + krow_in16) * STRH +
                                16 * kb + kdim8) * 2;
                    uint32_t b0, b1, b2, b3;
                    ldsm_x4(b0, b1, b2, b3, kaddr);
                    mma_f16(s[2 * nbp], qf[kb][0], qf[kb][1], qf[kb][2],
                            qf[kb][3], b0, b1);
                    mma_f16(s[2 * nbp + 1], qf[kb][0], qf[kb][1], qf[kb][2],
                            qf[kb][3], b2, b3);
                }
            }

            // masks: additive pad bias + predicated causal
            const bool needC = (k0 + 63 > q0 + warp * 16);
#pragma unroll
            for (int nb = 0; nb < 8; nb++) {
                const int cg = k0 + nb * 8 + 2 * tig;
                const float b0 = sB[rb + nb * 8 + 2 * tig];
                const float b1 = sB[rb + nb * 8 + 2 * tig + 1];
                s[nb][0] += b0; s[nb][2] += b0;
                s[nb][1] += b1; s[nb][3] += b1;
                if (needC) {
                    if (cg > rowg0)     s[nb][0] = kPad;
                    if (cg + 1 > rowg0) s[nb][1] = kPad;
                    if (cg > rowg1)     s[nb][2] = kPad;
                    if (cg + 1 > rowg1) s[nb][3] = kPad;
                }
            }

            // online softmax (base 2), P in registers
            float rmax0 = kPad, rmax1 = kPad;
#pragma unroll
            for (int nb = 0; nb < 8; nb++) {
                rmax0 = fmaxf(rmax0, fmaxf(s[nb][0], s[nb][1]));
                rmax1 = fmaxf(rmax1, fmaxf(s[nb][2], s[nb][3]));
            }
            rmax0 = fmaxf(rmax0, __shfl_xor_sync(0xffffffffu, rmax0, 1));
            rmax0 = fmaxf(rmax0, __shfl_xor_sync(0xffffffffu, rmax0, 2));
            rmax1 = fmaxf(rmax1, __shfl_xor_sync(0xffffffffu, rmax1, 1));
            rmax1 = fmaxf(rmax1, __shfl_xor_sync(0xffffffffu, rmax1, 2));
            const float mn0 = fmaxf(m0, rmax0);
            const float mn1 = fmaxf(m1, rmax1);
            const float corr0 = ex2f(m0 - mn0);
            const float corr1 = ex2f(m1 - mn1);
            float rs0 = 0.f, rs1 = 0.f;
#pragma unroll
            for (int nb = 0; nb < 8; nb++) {
                s[nb][0] = ex2f(s[nb][0] - mn0);
                s[nb][1] = ex2f(s[nb][1] - mn0);
                s[nb][2] = ex2f(s[nb][2] - mn1);
                s[nb][3] = ex2f(s[nb][3] - mn1);
                rs0 += s[nb][0] + s[nb][1];
                rs1 += s[nb][2] + s[nb][3];
            }
            rs0 += __shfl_xor_sync(0xffffffffu, rs0, 1);
            rs0 += __shfl_xor_sync(0xffffffffu, rs0, 2);
            rs1 += __shfl_xor_sync(0xffffffffu, rs1, 1);
            rs1 += __shfl_xor_sync(0xffffffffu, rs1, 2);
            l0 = l0 * corr0 + rs0; m0 = mn0;
            l1 = l1 * corr1 + rs1; m1 = mn1;
#pragma unroll
            for (int nb = 0; nb < 8; nb++) {
                o[nb][0] *= corr0; o[nb][1] *= corr0;
                o[nb][2] *= corr1; o[nb][3] *= corr1;
            }

            // O += P V (B via ldmatrix.x4.trans)
#pragma unroll
            for (int t = 0; t < 4; t++) {
                const uint32_t a0 = f2h2(s[2 * t][0], s[2 * t][1]);
                const uint32_t a1 = f2h2(s[2 * t][2], s[2 * t][3]);
                const uint32_t a2 = f2h2(s[2 * t + 1][0], s[2 * t + 1][1]);
                const uint32_t a3 = f2h2(s[2 * t + 1][2], s[2 * t + 1][3]);
                const uint32_t addr0 =
                    vbase + ((rb + 16 * t + lrow) * STRH + 8 * lhi) * 2;
#pragma unroll
                for (int nbp = 0; nbp < 4; nbp++) {
                    uint32_t b0, b1, b2, b3;
                    ldsm_x4_trans(b0, b1, b2, b3, addr0 + nbp * 32);
                    mma_f16(o[2 * nbp], a0, a1, a2, a3, b0, b1);
                    mma_f16(o[2 * nbp + 1], a0, a1, a2, a3, b2, b3);
                }
            }
        }
    }

    // ---- finalize -----------------------------------------------------------
    const float inv0 = 1.f / l0;
    const float inv1 = 1.f / l1;
    float* Og = O + (size_t)bn * kT * kD;
#pragma unroll
    for (int nb = 0; nb < 8; nb++) {
        *(float2*)(Og + (size_t)rowg0 * kD + nb * 8 + 2 * tig) =
            make_float2(o[nb][0] * inv0, o[nb][1] * inv0);
        *(float2*)(Og + (size_t)rowg1 * kD + nb * 8 + 2 * tig) =
            make_float2(o[nb][2] * inv1, o[nb][3] * inv1);
    }
}

extern "C" void kernel_launch(void* const* d_in, const int* in_sizes, int n_in,
                              void* d_out, int out_size) {
    const float* q = (const float*)d_in[0];
    const float* k = (const float*)d_in[1];
    const float* v = (const float*)d_in[2];
    float* o = (float*)d_out;

    const size_t smem_bytes = (size_t)SMEM_WORDS * sizeof(float);  // 36.5 KB
    cudaFuncSetAttribute(attn_fp16_r2_kernel,
                         cudaFuncAttributeMaxDynamicSharedMemorySize,
                         (int)smem_bytes);

    dim3 grid(kT / BM, 64);   // 8 x 64 = 512 blocks
    attn_fp16_r2_kernel<<<grid, THREADS, smem_bytes>>>(q, k, v, o);
}